// round 16
// baseline (speedup 1.0000x reference)
#include <cuda_runtime.h>
#include <cuda_bf16.h>
#include <math.h>

#define T_TOKENS 8192
#define HID      1024
#define NE       64
#define TOPK     8
#define INTER    512
#define TK       (T_TOKENS * TOPK)     // 65536 (token, expert) pairs
#define TILE_M   64
#define MAX_TILES (TK / TILE_M + NE)   // 1088

typedef __nv_bfloat16 bf16;

// ----------------------------------------------------------------------------
// Tiny device globals only (~1 MiB): harness memory guard counts lazily
// committed statics, so all large scratch lives in SMEM of the fused kernel.
// ----------------------------------------------------------------------------
__device__ int   g_indices[TK];
__device__ float g_rweight[TK];
__device__ int   g_row_token[TK];      // slot -> token
__device__ float g_slot_w[TK];         // slot -> routing weight
__device__ int   g_counts[NE];
__device__ int   g_fill[NE];
__device__ int   g_offsets[NE + 1];
__device__ int   g_tile_off[NE + 1];   // 64-row tiles
__device__ int   g_total_tiles;

// ----------------------------------------------------------------------------
__global__ void init_kernel() {
    int i = threadIdx.x;
    if (i < NE) { g_counts[i] = 0; g_fill[i] = 0; }
}

__global__ void zero_out_kernel(float* __restrict__ out) {
    size_t i = (size_t)blockIdx.x * blockDim.x + threadIdx.x;
    *(float4*)&out[i * 4] = make_float4(0.f, 0.f, 0.f, 0.f);
}

// ----------------------------------------------------------------------------
// fp32 pair -> bf16 hi-pair u32 + bf16 residual-pair u32
// ----------------------------------------------------------------------------
__device__ __forceinline__ void split_pack(float a, float b,
                                           unsigned& hi, unsigned& lo) {
    __nv_bfloat162 h = __float22bfloat162_rn(make_float2(a, b));
    float2 hf = __bfloat1622float2(h);
    __nv_bfloat162 l = __float22bfloat162_rn(make_float2(a - hf.x, b - hf.y));
    hi = *(unsigned*)&h;
    lo = *(unsigned*)&l;
}

// ----------------------------------------------------------------------------
// Router (fp32, exact): logits -> top8 -> softmax over top8
// ----------------------------------------------------------------------------
__global__ void __launch_bounds__(256) router_kernel(const float* __restrict__ x,
                                                     const float* __restrict__ rw) {
    __shared__ float Xs[16][128];
    __shared__ float RWs[128][64];
    __shared__ float Ls[16][64];

    int tid = threadIdx.x;
    int t0  = blockIdx.x * 16;
    int e   = tid & 63;
    int tg  = tid >> 6;

    float acc0 = 0.f, acc1 = 0.f, acc2 = 0.f, acc3 = 0.f;

    for (int h0 = 0; h0 < HID; h0 += 128) {
        #pragma unroll
        for (int r = 0; r < 2; r++) {
            int f = tid + 256 * r;
            int tok = f >> 5, c4 = f & 31;
            *(float4*)&Xs[tok][c4 * 4] =
                *(const float4*)&x[(size_t)(t0 + tok) * HID + h0 + c4 * 4];
        }
        #pragma unroll
        for (int r = 0; r < 8; r++) {
            int f = tid + 256 * r;
            int hh = f >> 4, e4 = f & 15;
            *(float4*)&RWs[hh][e4 * 4] =
                *(const float4*)&rw[(size_t)(h0 + hh) * NE + e4 * 4];
        }
        __syncthreads();
        #pragma unroll 4
        for (int hh = 0; hh < 128; hh++) {
            float w = RWs[hh][e];
            acc0 += Xs[tg * 4 + 0][hh] * w;
            acc1 += Xs[tg * 4 + 1][hh] * w;
            acc2 += Xs[tg * 4 + 2][hh] * w;
            acc3 += Xs[tg * 4 + 3][hh] * w;
        }
        __syncthreads();
    }
    Ls[tg * 4 + 0][e] = acc0;
    Ls[tg * 4 + 1][e] = acc1;
    Ls[tg * 4 + 2][e] = acc2;
    Ls[tg * 4 + 3][e] = acc3;
    __syncthreads();

    if (tid < 16) {
        int t = tid;
        int   idx[TOPK];
        float val[TOPK];
        #pragma unroll
        for (int k = 0; k < TOPK; k++) {
            float best = -1e30f; int bi = 0;
            for (int ee = 0; ee < NE; ee++) {
                float v = Ls[t][ee];
                if (v > best) { best = v; bi = ee; }
            }
            idx[k] = bi; val[k] = best;
            Ls[t][bi] = -1e30f;
        }
        float m = val[0], s = 0.f, w[TOPK];
        #pragma unroll
        for (int k = 0; k < TOPK; k++) { w[k] = expf(val[k] - m); s += w[k]; }
        float inv = 1.f / s;
        int base = (t0 + t) * TOPK;
        #pragma unroll
        for (int k = 0; k < TOPK; k++) {
            g_indices[base + k] = idx[k];
            g_rweight[base + k] = w[k] * inv;
            atomicAdd(&g_counts[idx[k]], 1);
        }
    }
}

// ----------------------------------------------------------------------------
__global__ void scan_kernel() {
    int off = 0, toff = 0;
    g_offsets[0] = 0; g_tile_off[0] = 0;
    for (int e = 0; e < NE; e++) {
        off  += g_counts[e];               g_offsets[e + 1]  = off;
        toff += (g_counts[e] + 63) >> 6;   g_tile_off[e + 1] = toff;
    }
    g_total_tiles = toff;
}

__global__ void scatter_kernel() {
    int i = blockIdx.x * blockDim.x + threadIdx.x;
    if (i >= TK) return;
    int e    = g_indices[i];
    int pos  = atomicAdd(&g_fill[e], 1);
    int slot = g_offsets[e] + pos;
    g_row_token[slot] = i >> 3;
    g_slot_w[slot]    = g_rweight[i];
}

// ----------------------------------------------------------------------------
__device__ __forceinline__ void mma_bf16(float* c, const unsigned* a, const unsigned* b) {
    asm volatile(
        "mma.sync.aligned.m16n8k16.row.col.f32.bf16.bf16.f32 "
        "{%0,%1,%2,%3}, {%4,%5,%6,%7}, {%8,%9}, {%0,%1,%2,%3};"
        : "+f"(c[0]), "+f"(c[1]), "+f"(c[2]), "+f"(c[3])
        : "r"(a[0]), "r"(a[1]), "r"(a[2]), "r"(a[3]), "r"(b[0]), "r"(b[1]));
}

// dynamic SMEM partition (u32 units). k-chunk = 64 -> 32 k-pairs + 4 pad = 36.
// Fragment reads: bank = (36*r + c) mod 32 = (4r + c) mod 32, r=gq(8) x c=tq(4)
// -> all 32 banks distinct: conflict-free. act rows keep stride 260.
#define U_AS_HI  0u        // 64 rows x 36
#define U_AS_LO  2304u
#define U_BS_HI  4608u     // 256 rows x 36
#define U_BS_LO  13824u
#define U_ACT_HI 23040u    // 64 rows x 260
#define U_ACT_LO 39680u
#define U_TOTAL  56320u
#define SMEM_BYTES (U_TOTAL * 4)   // 225280

// ----------------------------------------------------------------------------
// Fused expert kernel: one 64-row slot tile per block, 256 threads (8 warps,
// warp grid 2m x 4n, warp tile 32x32). 3-term bf16-split MMA
// (C += Ah*Bh + Ah*Bl + Al*Bh). Structure IDENTICAL to the 2623us kernel
// (single-buffered load->stage->sync->mma->sync; staging registers die before
// fragment registers go live), with ONE change: k-chunk 32 -> 64, halving the
// number of syncs/loop iterations the fixed per-chunk overhead is paid on.
// ----------------------------------------------------------------------------
__global__ void __launch_bounds__(256) fused_moe_kernel(
    const float* __restrict__ x, const float* __restrict__ wgu,
    const float* __restrict__ wd, float* __restrict__ out) {

    extern __shared__ unsigned sm[];

    int bm = blockIdx.x;
    if (bm >= g_total_tiles) return;
    int e = 0;
    while (e < NE - 1 && g_tile_off[e + 1] <= bm) e++;
    int row_start  = g_offsets[e] + (bm - g_tile_off[e]) * TILE_M;
    int rows_valid = g_offsets[e + 1] - row_start;
    if (rows_valid > TILE_M) rows_valid = TILE_M;

    int tid  = threadIdx.x;
    int lane = tid & 31;
    int wid  = tid >> 5;
    int wm   = (wid >> 2) * 32;    // warp m offset (0/32)
    int wn   = (wid & 3) * 32;     // warp n offset (0..96)
    int gq   = lane >> 2;
    int tq   = lane & 3;

    // A loader: row = tid>>2 (0..63), 16-float granule = tid&3 (64 k/chunk)
    int arow = tid >> 2, g4 = tid & 3;
    int ar   = arow < rows_valid ? arow : 0;
    const float* afp = x + (size_t)g_row_token[row_start + ar] * HID + g4 * 16;
    int as_w = arow * 36 + g4 * 8;

    // Phase A B loader: one n-row (0..255; gate<128, up>=128), 64 k per chunk
    int bnA = tid;
    // Phase B loader: one n-row (0..127) x one 32-k half
    int bnB = tid & 127, bkhB = tid >> 7;

    const float* wgu_e = wgu + (size_t)e * HID * 1024;
    const float* wd_e  = wd + (size_t)e * INTER * 1024;

    // =========================== Phase A ===========================
    for (int nc = 0; nc < 4; nc++) {
        int gcol = (bnA < 128) ? (nc * 128 + bnA) : (512 + nc * 128 + (bnA - 128));
        const float* wpA = wgu_e + gcol;

        float accg[2][4][4], accu[2][4][4];
        #pragma unroll
        for (int mi = 0; mi < 2; mi++)
            #pragma unroll
            for (int ni = 0; ni < 4; ni++)
                #pragma unroll
                for (int q = 0; q < 4; q++) { accg[mi][ni][q] = 0.f; accu[mi][ni][q] = 0.f; }

        // stage one 64-k chunk (A: 16 floats/thread; B: 64 floats/thread in
        // 4 groups of 16 so the live set stays small)
        auto stageA = [&](int k0) {
            #pragma unroll
            for (int gseg = 0; gseg < 2; gseg++) {
                float4 v0 = *(const float4*)(afp + k0 + gseg * 8);
                float4 v1 = *(const float4*)(afp + k0 + gseg * 8 + 4);
                uint4 ha, la;
                split_pack(v0.x, v0.y, ha.x, la.x);
                split_pack(v0.z, v0.w, ha.y, la.y);
                split_pack(v1.x, v1.y, ha.z, la.z);
                split_pack(v1.z, v1.w, ha.w, la.w);
                *(uint4*)&sm[U_AS_HI + as_w + gseg * 4] = ha;
                *(uint4*)&sm[U_AS_LO + as_w + gseg * 4] = la;
            }
            #pragma unroll
            for (int grp = 0; grp < 4; grp++) {
                float v[16];
                const float* bp = wpA + (size_t)(k0 + grp * 16) * 1024;
                #pragma unroll
                for (int kk = 0; kk < 16; kk++) v[kk] = bp[(size_t)kk * 1024];
                unsigned h[8], l[8];
                #pragma unroll
                for (int p = 0; p < 8; p++)
                    split_pack(v[2 * p], v[2 * p + 1], h[p], l[p]);
                unsigned o = (unsigned)bnA * 36u + grp * 8u;
                *(uint4*)&sm[U_BS_HI + o]      = *(uint4*)&h[0];
                *(uint4*)&sm[U_BS_HI + o + 4u] = *(uint4*)&h[4];
                *(uint4*)&sm[U_BS_LO + o]      = *(uint4*)&l[0];
                *(uint4*)&sm[U_BS_LO + o + 4u] = *(uint4*)&l[4];
            }
        };
        auto mmaA = [&]() {
            #pragma unroll
            for (int ks = 0; ks < 4; ks++) {
                unsigned Ah[2][4], Al[2][4];
                #pragma unroll
                for (int mi = 0; mi < 2; mi++) {
                    unsigned ra = (unsigned)(wm + mi * 16 + gq) * 36u + ks * 8u;
                    Ah[mi][0] = sm[U_AS_HI + ra + tq];
                    Ah[mi][1] = sm[U_AS_HI + ra + 288 + tq];
                    Ah[mi][2] = sm[U_AS_HI + ra + tq + 4];
                    Ah[mi][3] = sm[U_AS_HI + ra + 288 + tq + 4];
                    Al[mi][0] = sm[U_AS_LO + ra + tq];
                    Al[mi][1] = sm[U_AS_LO + ra + 288 + tq];
                    Al[mi][2] = sm[U_AS_LO + ra + tq + 4];
                    Al[mi][3] = sm[U_AS_LO + ra + 288 + tq + 4];
                }
                #pragma unroll
                for (int ni = 0; ni < 4; ni++) {
                    unsigned rg = (unsigned)(wn + ni * 8 + gq) * 36u + ks * 8u;
                    unsigned ru = rg + 4608u;   // +128 rows * 36
                    unsigned Bgh[2] = { sm[U_BS_HI + rg + tq], sm[U_BS_HI + rg + tq + 4] };
                    unsigned Bgl[2] = { sm[U_BS_LO + rg + tq], sm[U_BS_LO + rg + tq + 4] };
                    unsigned Buh[2] = { sm[U_BS_HI + ru + tq], sm[U_BS_HI + ru + tq + 4] };
                    unsigned Bul[2] = { sm[U_BS_LO + ru + tq], sm[U_BS_LO + ru + tq + 4] };
                    #pragma unroll
                    for (int mi = 0; mi < 2; mi++) {
                        mma_bf16(accg[mi][ni], Ah[mi], Bgh);
                        mma_bf16(accg[mi][ni], Ah[mi], Bgl);
                        mma_bf16(accg[mi][ni], Al[mi], Bgh);
                        mma_bf16(accu[mi][ni], Ah[mi], Buh);
                        mma_bf16(accu[mi][ni], Ah[mi], Bul);
                        mma_bf16(accu[mi][ni], Al[mi], Buh);
                    }
                }
            }
        };

        for (int k0 = 0; k0 < HID; k0 += 64) {
            stageA(k0);
            __syncthreads();
            mmaA();
            __syncthreads();
        }

        // SiLU epilogue -> act SMEM (bf16 hi/lo k-pairs, stride 260)
        #pragma unroll
        for (int mi = 0; mi < 2; mi++) {
            int r0 = wm + mi * 16 + gq, r1 = r0 + 8;
            #pragma unroll
            for (int ni = 0; ni < 4; ni++) {
                int cidx = nc * 64 + (wn >> 1) + ni * 4 + tq;
                float gA = accg[mi][ni][0], gB = accg[mi][ni][1];
                float p0 = gA / (1.f + expf(-gA)) * accu[mi][ni][0];
                float p1 = gB / (1.f + expf(-gB)) * accu[mi][ni][1];
                unsigned h, l;
                split_pack(p0, p1, h, l);
                sm[U_ACT_HI + r0 * 260 + cidx] = h;
                sm[U_ACT_LO + r0 * 260 + cidx] = l;
                gA = accg[mi][ni][2]; gB = accg[mi][ni][3];
                p0 = gA / (1.f + expf(-gA)) * accu[mi][ni][2];
                p1 = gB / (1.f + expf(-gB)) * accu[mi][ni][3];
                split_pack(p0, p1, h, l);
                sm[U_ACT_HI + r1 * 260 + cidx] = h;
                sm[U_ACT_LO + r1 * 260 + cidx] = l;
            }
        }
    }
    __syncthreads();   // act complete before Phase B reads

    // =========================== Phase B ===========================
    for (int nc2 = 0; nc2 < 8; nc2++) {
        int n0 = nc2 * 128;
        const float* wpB = wd_e + n0 + bnB;

        float acc[2][4][4];
        #pragma unroll
        for (int mi = 0; mi < 2; mi++)
            #pragma unroll
            for (int ni = 0; ni < 4; ni++)
                #pragma unroll
                for (int q = 0; q < 4; q++) acc[mi][ni][q] = 0.f;

        auto stageB = [&](int k0) {
            #pragma unroll
            for (int grp = 0; grp < 2; grp++) {
                float v[16];
                const float* bp = wpB + (size_t)(k0 + bkhB * 32 + grp * 16) * 1024;
                #pragma unroll
                for (int kk = 0; kk < 16; kk++) v[kk] = bp[(size_t)kk * 1024];
                unsigned h[8], l[8];
                #pragma unroll
                for (int p = 0; p < 8; p++)
                    split_pack(v[2 * p], v[2 * p + 1], h[p], l[p]);
                unsigned o = (unsigned)bnB * 36u + (unsigned)bkhB * 16u + grp * 8u;
                *(uint4*)&sm[U_BS_HI + o]      = *(uint4*)&h[0];
                *(uint4*)&sm[U_BS_HI + o + 4u] = *(uint4*)&h[4];
                *(uint4*)&sm[U_BS_LO + o]      = *(uint4*)&l[0];
                *(uint4*)&sm[U_BS_LO + o + 4u] = *(uint4*)&l[4];
            }
        };
        auto mmaB = [&](int k0) {
            #pragma unroll
            for (int ks = 0; ks < 4; ks++) {
                unsigned Ah[2][4], Al[2][4];
                #pragma unroll
                for (int mi = 0; mi < 2; mi++) {
                    unsigned ab = (unsigned)(wm + mi * 16 + gq) * 260u
                                + (unsigned)(k0 >> 1) + ks * 8u;
                    Ah[mi][0] = sm[U_ACT_HI + ab + tq];
                    Ah[mi][1] = sm[U_ACT_HI + ab + 2080 + tq];
                    Ah[mi][2] = sm[U_ACT_HI + ab + tq + 4];
                    Ah[mi][3] = sm[U_ACT_HI + ab + 2080 + tq + 4];
                    Al[mi][0] = sm[U_ACT_LO + ab + tq];
                    Al[mi][1] = sm[U_ACT_LO + ab + 2080 + tq];
                    Al[mi][2] = sm[U_ACT_LO + ab + tq + 4];
                    Al[mi][3] = sm[U_ACT_LO + ab + 2080 + tq + 4];
                }
                #pragma unroll
                for (int ni = 0; ni < 4; ni++) {
                    unsigned rb = (unsigned)(wn + ni * 8 + gq) * 36u + ks * 8u;
                    unsigned Bh[2] = { sm[U_BS_HI + rb + tq], sm[U_BS_HI + rb + tq + 4] };
                    unsigned Bl[2] = { sm[U_BS_LO + rb + tq], sm[U_BS_LO + rb + tq + 4] };
                    #pragma unroll
                    for (int mi = 0; mi < 2; mi++) {
                        mma_bf16(acc[mi][ni], Ah[mi], Bh);
                        mma_bf16(acc[mi][ni], Ah[mi], Bl);
                        mma_bf16(acc[mi][ni], Al[mi], Bh);
                    }
                }
            }
        };

        for (int k0 = 0; k0 < INTER; k0 += 64) {
            stageB(k0);
            __syncthreads();
            mmaB(k0);
            __syncthreads();
        }

        // fused combine: out[token] += w_slot * val
        #pragma unroll
        for (int mi = 0; mi < 2; mi++) {
            int r0 = wm + mi * 16 + gq, r1 = r0 + 8;
            bool v0 = r0 < rows_valid, v1 = r1 < rows_valid;
            int   t0v = 0, t1v = 0;
            float w0 = 0.f, w1 = 0.f;
            if (v0) { t0v = g_row_token[row_start + r0]; w0 = g_slot_w[row_start + r0]; }
            if (v1) { t1v = g_row_token[row_start + r1]; w1 = g_slot_w[row_start + r1]; }
            #pragma unroll
            for (int ni = 0; ni < 4; ni++) {
                int col = n0 + wn + ni * 8 + tq * 2;
                if (v0) {
                    float* o = &out[(size_t)t0v * 1024 + col];
                    atomicAdd(o,     w0 * acc[mi][ni][0]);
                    atomicAdd(o + 1, w0 * acc[mi][ni][1]);
                }
                if (v1) {
                    float* o = &out[(size_t)t1v * 1024 + col];
                    atomicAdd(o,     w1 * acc[mi][ni][2]);
                    atomicAdd(o + 1, w1 * acc[mi][ni][3]);
                }
            }
        }
    }
}

// ----------------------------------------------------------------------------
extern "C" void kernel_launch(void* const* d_in, const int* in_sizes, int n_in,
                              void* d_out, int out_size) {
    const float* x   = (const float*)d_in[0];   // [8192, 1024]
    const float* rw  = (const float*)d_in[1];   // [1024, 64]
    const float* wgu = (const float*)d_in[2];   // [64, 1024, 1024]
    const float* wd  = (const float*)d_in[3];   // [64, 512, 1024]
    float* out = (float*)d_out;                 // [8192, 1024]

    static bool attr_set = false;
    if (!attr_set) {
        cudaFuncSetAttribute(fused_moe_kernel,
                             cudaFuncAttributeMaxDynamicSharedMemorySize,
                             SMEM_BYTES);
        attr_set = true;
    }

    init_kernel<<<1, 64>>>();
    zero_out_kernel<<<(T_TOKENS * HID / 4) / 256, 256>>>(out);
    router_kernel<<<T_TOKENS / 16, 256>>>(x, rw);
    scan_kernel<<<1, 1>>>();
    scatter_kernel<<<TK / 256, 256>>>();
    fused_moe_kernel<<<MAX_TILES, 256, SMEM_BYTES>>>(x, wgu, wd, out);
}